// round 6
// baseline (speedup 1.0000x reference)
#include <cuda_runtime.h>
#include <math.h>

#define BATCH   64
#define HID     512
#define EMBD    200
#define VOCAB   32000
#define SRCLEN  64
#define TGTLEN  64
#define FC_TILE 128
#define FC_BLOCKS (VOCAB / FC_TILE)

typedef unsigned long long ull;

__device__ __forceinline__ ull pack2(float a, float b) {
    ull r; asm("mov.b64 %0, {%1,%2};" : "=l"(r) : "f"(a), "f"(b)); return r;
}
__device__ __forceinline__ ull ffma2(ull a, ull b, ull c) {
    ull d; asm("fma.rn.f32x2 %0, %1, %2, %3;" : "=l"(d) : "l"(a), "l"(b), "l"(c)); return d;
}
__device__ __forceinline__ float2 unpk(ull v) {
    float2 r; asm("mov.b64 {%0,%1}, %2;" : "=f"(r.x), "=f"(r.y) : "l"(v)); return r;
}

// static scratch (allocation-free rule)
__device__ float g_gpart[4][BATCH][4*HID];
__device__ float g_h0[BATCH*HID], g_c0[BATCH*HID];
__device__ float g_h1[BATCH*HID], g_c1[BATCH*HID];
__device__ int   g_xtok[BATCH];
__device__ float g_pval[FC_BLOCKS*BATCH];
__device__ int   g_pidx[FC_BLOCKS*BATCH];

__global__ void init_kernel(const int* __restrict__ target) {
    int i = blockIdx.x*blockDim.x + threadIdx.x;
    if (i < BATCH*HID) { g_h0[i]=0.f; g_c0[i]=0.f; g_h1[i]=0.f; g_c1[i]=0.f; }
    if (i < BATCH) g_xtok[i] = target[i];
}

// gates[64][2048] = X @ Wih^T + Hprev @ Whh^T, split into 4 K-partials (grid.y)
__global__ void lstm_gates_kernel(
    const float* __restrict__ Wih, int Kih, const float* __restrict__ Whh,
    const float* __restrict__ emb, const int* __restrict__ toks,
    int use_xtok, int layer)
{
    __shared__ __align__(16) float Wt[8*66];
    __shared__ __align__(16) float Xs[8*66];
    __shared__ int stoks[BATCH];

    int tid = threadIdx.x, y = blockIdx.y, j0 = blockIdx.x*64;
    const float* hprev = layer ? g_h1 : g_h0;
    const float* W; int ldW; const float* X; int ldX;
    int gather = 0, kbeg, kend;
    if (y < 2) {
        W = Wih; ldW = Kih;
        if (layer == 0) { X = emb; ldX = EMBD; gather = 1; }
        else            { X = g_h0; ldX = HID; }
        int kh = ((Kih/2) + 7) & ~7;
        kbeg = (y==0) ? 0 : kh;  kend = (y==0) ? kh : Kih;
    } else {
        W = Whh; ldW = HID; X = hprev; ldX = HID;
        kbeg = (y==2) ? 0 : 256; kend = (y==2) ? 256 : 512;
    }
    if (tid < BATCH)
        stoks[tid] = gather ? (use_xtok ? g_xtok[tid] : toks[tid]) : tid;
    __syncthreads();

    ull acc[4][2];
    #pragma unroll
    for (int r = 0; r < 4; ++r) { acc[r][0]=0ULL; acc[r][1]=0ULL; }

    int rg = tid>>4, cg = tid&15, kk = tid&7, jj = tid>>3;

    for (int k0 = kbeg; k0 < kend; k0 += 8) {
        int kg = k0 + kk, inb = (kg < kend);
        #pragma unroll
        for (int p = 0; p < 2; ++p) {
            int j = jj + p*32;
            Wt[kk*66 + j] = inb ? W[(size_t)(j0+j)*ldW + kg] : 0.f;
            Xs[kk*66 + j] = inb ? X[(size_t)stoks[j]*ldX + kg] : 0.f;
        }
        __syncthreads();
        #pragma unroll
        for (int q = 0; q < 8; ++q) {
            ull w0 = *(const ull*)&Wt[q*66 + cg*4];
            ull w1 = *(const ull*)&Wt[q*66 + cg*4 + 2];
            #pragma unroll
            for (int r = 0; r < 4; ++r) {
                float xv = Xs[q*66 + rg*4 + r];
                ull x2 = pack2(xv, xv);
                acc[r][0] = ffma2(x2, w0, acc[r][0]);
                acc[r][1] = ffma2(x2, w1, acc[r][1]);
            }
        }
        __syncthreads();
    }
    #pragma unroll
    for (int r = 0; r < 4; ++r) {
        float2 v0 = unpk(acc[r][0]), v1 = unpk(acc[r][1]);
        *(float4*)&g_gpart[y][rg*4+r][j0 + cg*4] = make_float4(v0.x,v0.y,v1.x,v1.y);
    }
}

// fixed-order partial sum + biases + activations + state update
__global__ void lstm_epilogue_kernel(const float* __restrict__ bih,
                                     const float* __restrict__ bhh, int layer)
{
    int idx = blockIdx.x*blockDim.x + threadIdx.x;
    int b = idx >> 9, jj = idx & 511;
    float* h = layer ? g_h1 : g_h0;
    float* c = layer ? g_c1 : g_c0;
    float s[4];
    #pragma unroll
    for (int g = 0; g < 4; ++g) {
        int col = g*512 + jj;
        float v = bih[col] + bhh[col];
        #pragma unroll
        for (int y = 0; y < 4; ++y) v += g_gpart[y][b][col];
        s[g] = v;
    }
    float iv = 1.f/(1.f+expf(-s[0]));
    float fv = 1.f/(1.f+expf(-s[1]));
    float gv = tanhf(s[2]);
    float ov = 1.f/(1.f+expf(-s[3]));
    float cn = fv*c[idx] + iv*gv;
    c[idx] = cn;
    h[idx] = ov*tanhf(cn);
}

// logits tile [64 x 128] + per-block argmax partial (lowest-index ties)
__global__ void fc_argmax_kernel(const float* __restrict__ fcW,
                                 const float* __restrict__ fcb,
                                 float* __restrict__ out)
{
    __shared__ __align__(16) float Wt[8*130];
    __shared__ __align__(16) float Hs[8*66];
    __shared__ float rval[BATCH*16];
    __shared__ int   ridx[BATCH*16];

    int tid = threadIdx.x, v0 = blockIdx.x*FC_TILE;
    int rg = tid>>4, cg = tid&15, kk = tid&7, jj = tid>>3;

    ull acc[4][4];
    #pragma unroll
    for (int r = 0; r < 4; ++r)
        #pragma unroll
        for (int q = 0; q < 4; ++q) acc[r][q] = 0ULL;

    for (int k0 = 0; k0 < HID; k0 += 8) {
        int kg = k0 + kk;
        #pragma unroll
        for (int p = 0; p < 4; ++p)
            Wt[kk*130 + jj + p*32] = fcW[(size_t)(v0 + jj + p*32)*HID + kg];
        #pragma unroll
        for (int p = 0; p < 2; ++p)
            Hs[kk*66 + jj + p*32] = g_h1[(size_t)(jj + p*32)*HID + kg];
        __syncthreads();
        #pragma unroll
        for (int q = 0; q < 8; ++q) {
            ull w[4];
            #pragma unroll
            for (int u = 0; u < 4; ++u) w[u] = *(const ull*)&Wt[q*130 + cg*8 + u*2];
            #pragma unroll
            for (int r = 0; r < 4; ++r) {
                float xv = Hs[q*66 + rg*4 + r];
                ull x2 = pack2(xv, xv);
                #pragma unroll
                for (int u = 0; u < 4; ++u) acc[r][u] = ffma2(x2, w[u], acc[r][u]);
            }
        }
        __syncthreads();
    }

    float bv[8];
    #pragma unroll
    for (int u = 0; u < 8; ++u) bv[u] = fcb[v0 + cg*8 + u];

    #pragma unroll
    for (int r = 0; r < 4; ++r) {
        int b = rg*4 + r;
        float vals[8];
        #pragma unroll
        for (int u = 0; u < 4; ++u) {
            float2 t = unpk(acc[r][u]);
            vals[2*u] = t.x + bv[2*u]; vals[2*u+1] = t.y + bv[2*u+1];
        }
        float* p = out + (size_t)b*VOCAB + v0 + cg*8;
        *(float4*)p       = make_float4(vals[0],vals[1],vals[2],vals[3]);
        *(float4*)(p + 4) = make_float4(vals[4],vals[5],vals[6],vals[7]);
        float best = vals[0]; int bi = 0;
        #pragma unroll
        for (int u = 1; u < 8; ++u)
            if (vals[u] > best) { best = vals[u]; bi = u; }
        rval[b*16 + cg] = best; ridx[b*16 + cg] = v0 + cg*8 + bi;
    }
    __syncthreads();
    if (tid < BATCH) {
        float best = rval[tid*16]; int bi = ridx[tid*16];
        #pragma unroll
        for (int u = 1; u < 16; ++u) {
            float v = rval[tid*16 + u];
            if (v > best) { best = v; bi = ridx[tid*16 + u]; }
        }
        g_pval[blockIdx.x*BATCH + tid] = best;
        g_pidx[blockIdx.x*BATCH + tid] = bi;
    }
}

// final argmax (ascending scan, lowest-index ties) + token select
__global__ void argmax_token_kernel(const int* __restrict__ target,
                                    const int* __restrict__ tfmask, int t)
{
    __shared__ float sv[256];
    __shared__ int   si[256];
    int tid = threadIdx.x, b = tid>>2, seg = tid&3;
    const int per = (FC_BLOCKS + 3) / 4;
    int s0 = seg*per, s1 = s0 + per; if (s1 > FC_BLOCKS) s1 = FC_BLOCKS;
    float best = -3.4e38f; int bi = 0;
    for (int q = s0; q < s1; ++q) {
        float v = g_pval[q*BATCH + b];
        if (v > best) { best = v; bi = g_pidx[q*BATCH + b]; }
    }
    sv[tid] = best; si[tid] = bi;
    __syncthreads();
    if (seg == 0) {
        #pragma unroll
        for (int u = 1; u < 4; ++u) {
            float v = sv[tid + u];
            if (v > best) { best = v; bi = si[tid + u]; }
        }
        g_xtok[b] = (tfmask[t] > 0) ? target[t*BATCH + b] : bi;
    }
}

extern "C" void kernel_launch(void* const* d_in, const int* in_sizes, int n_in,
                              void* d_out, int out_size)
{
    const float *enc_embed,*dec_embed,*fcW,*fcb;
    const float *eWih0,*eWhh0,*ebih0,*ebhh0,*eWih1,*eWhh1,*ebih1,*ebhh1;
    const float *dWih0,*dWhh0,*dbih0,*dbhh0,*dWih1,*dWhh1,*dbih1,*dbhh1;
    const int *src,*target,*tfmask;

    if (in_sizes[0] == SRCLEN*BATCH) {
        // setup_inputs dict order
        src=(const int*)d_in[0]; target=(const int*)d_in[1]; tfmask=(const int*)d_in[2];
        enc_embed=(const float*)d_in[3]; dec_embed=(const float*)d_in[4];
        eWih0=(const float*)d_in[5];  eWhh0=(const float*)d_in[6];
        ebih0=(const float*)d_in[7];  ebhh0=(const float*)d_in[8];
        eWih1=(const float*)d_in[9];  eWhh1=(const float*)d_in[10];
        ebih1=(const float*)d_in[11]; ebhh1=(const float*)d_in[12];
        dWih0=(const float*)d_in[13]; dWhh0=(const float*)d_in[14];
        dbih0=(const float*)d_in[15]; dbhh0=(const float*)d_in[16];
        dWih1=(const float*)d_in[17]; dWhh1=(const float*)d_in[18];
        dbih1=(const float*)d_in[19]; dbhh1=(const float*)d_in[20];
        fcW=(const float*)d_in[21];   fcb=(const float*)d_in[22];
    } else {
        // reference() signature order
        enc_embed=(const float*)d_in[0];
        eWih0=(const float*)d_in[1];  eWhh0=(const float*)d_in[2];
        ebih0=(const float*)d_in[3];  ebhh0=(const float*)d_in[4];
        eWih1=(const float*)d_in[5];  eWhh1=(const float*)d_in[6];
        ebih1=(const float*)d_in[7];  ebhh1=(const float*)d_in[8];
        dec_embed=(const float*)d_in[9];
        dWih0=(const float*)d_in[10]; dWhh0=(const float*)d_in[11];
        dbih0=(const float*)d_in[12]; dbhh0=(const float*)d_in[13];
        dWih1=(const float*)d_in[14]; dWhh1=(const float*)d_in[15];
        dbih1=(const float*)d_in[16]; dbhh1=(const float*)d_in[17];
        fcW=(const float*)d_in[18];   fcb=(const float*)d_in[19];
        src=(const int*)d_in[20]; target=(const int*)d_in[21]; tfmask=(const int*)d_in[22];
    }

    float* out = (float*)d_out;
    cudaMemsetAsync(out, 0, (size_t)BATCH * VOCAB * sizeof(float));
    init_kernel<<<128, 256>>>(target);

    dim3 ggrid(32, 4);
    for (int s = 0; s < SRCLEN; ++s) {
        lstm_gates_kernel<<<ggrid,256>>>(eWih0, EMBD, eWhh0, enc_embed, src + s*BATCH, 0, 0);
        lstm_epilogue_kernel<<<128,256>>>(ebih0, ebhh0, 0);
        lstm_gates_kernel<<<ggrid,256>>>(eWih1, HID, eWhh1, (const float*)0, (const int*)0, 0, 1);
        lstm_epilogue_kernel<<<128,256>>>(ebih1, ebhh1, 1);
    }
    for (int t = 1; t < TGTLEN; ++t) {
        lstm_gates_kernel<<<ggrid,256>>>(dWih0, EMBD, dWhh0, dec_embed, (const int*)0, 1, 0);
        lstm_epilogue_kernel<<<128,256>>>(dbih0, dbhh0, 0);
        lstm_gates_kernel<<<ggrid,256>>>(dWih1, HID, dWhh1, (const float*)0, (const int*)0, 0, 1);
        lstm_epilogue_kernel<<<128,256>>>(dbih1, dbhh1, 1);
        fc_argmax_kernel<<<FC_BLOCKS,256>>>(fcW, fcb, out + (size_t)t*BATCH*VOCAB);
        argmax_token_kernel<<<1,256>>>(target, tfmask, t);
    }
}

// round 7
// speedup vs baseline: 1.6933x; 1.6933x over previous
#include <cuda_runtime.h>
#include <math.h>

#define BATCH   64
#define HID     512
#define EMBD    200
#define VOCAB   32000
#define SRCLEN  64
#define TGTLEN  64
#define FC_TILE 128
#define FC_BLOCKS (VOCAB / FC_TILE)
#define MAXSPLIT 16

typedef unsigned long long ull;

__device__ __forceinline__ ull pack2(float a, float b) {
    ull r; asm("mov.b64 %0, {%1,%2};" : "=l"(r) : "f"(a), "f"(b)); return r;
}
__device__ __forceinline__ ull ffma2(ull a, ull b, ull c) {
    ull d; asm("fma.rn.f32x2 %0, %1, %2, %3;" : "=l"(d) : "l"(a), "l"(b), "l"(c)); return d;
}
__device__ __forceinline__ float2 unpk(ull v) {
    float2 r; asm("mov.b64 {%0,%1}, %2;" : "=f"(r.x), "=f"(r.y) : "l"(v)); return r;
}

// static scratch (allocation-free rule)
__device__ float g_gpart[MAXSPLIT][BATCH][4*HID];
__device__ float g_h0[BATCH*HID], g_c0[BATCH*HID];
__device__ float g_h1[BATCH*HID], g_c1[BATCH*HID];
__device__ int   g_xtok[BATCH];
__device__ float g_pval[FC_BLOCKS*BATCH];
__device__ int   g_pidx[FC_BLOCKS*BATCH];

__global__ void init_kernel(const int* __restrict__ target) {
    int i = blockIdx.x*blockDim.x + threadIdx.x;
    if (i < BATCH*HID) { g_h0[i]=0.f; g_c0[i]=0.f; g_h1[i]=0.f; g_c1[i]=0.f; }
    if (i < BATCH) g_xtok[i] = target[i];
}

// ============================================================================
// LSTM gates: gates[64][2048] partial = X @ W^T over a K-slice.
// Block: 128 threads, tile 64 batch x 64 cols, per-thread 4b x 8c.
// grid = (32 col-blocks, nih + nhh K-splits). Partials -> g_gpart[y].
// ============================================================================
__global__ void __launch_bounds__(128) lstm_gates2(
    const float* __restrict__ Wih, int Kih, int nih, int ihsplit,
    const float* __restrict__ Whh,
    const float* __restrict__ emb, const int* __restrict__ toks,
    int use_xtok, int layer)
{
    __shared__ __align__(16) float Ws[8][64];
    __shared__ __align__(16) float Xs[8][64];
    __shared__ int stoks[64];

    int tid = threadIdx.x;
    int y = blockIdx.y, j0 = blockIdx.x*64;

    const float* W; const float* X; int ldW, ldX, kbeg, kend;
    int gather = 0;
    if (y < nih) {
        W = Wih; ldW = Kih;
        kbeg = y*ihsplit;
        kend = kbeg + ihsplit; if (kend > Kih) kend = Kih;
        if (layer == 0) { X = emb; ldX = EMBD; gather = 1; }
        else            { X = g_h0; ldX = HID; }
    } else {
        W = Whh; ldW = HID;
        int y2 = y - nih;
        kbeg = y2*64; kend = kbeg + 64;
        X = layer ? g_h1 : g_h0; ldX = HID;
    }
    if (tid < 64)
        stoks[tid] = gather ? (use_xtok ? g_xtok[tid] : toks[tid]) : tid;
    __syncthreads();

    int l = tid & 31, w = tid >> 5;
    int rg = (w & 1)*8 + (l & 7);     // 0..15 -> batch rows rg*4..+3
    int cg = (w >> 1)*4 + (l >> 3);   // 0..7  -> cols cg*8..+7
    int sj = tid & 63, shalf = tid >> 6;  // staging: element sj, k-half

    ull acc[4][4];
    #pragma unroll
    for (int r = 0; r < 4; ++r)
        #pragma unroll
        for (int u = 0; u < 4; ++u) acc[r][u] = 0ULL;

    const float* Wp = W + (size_t)(j0 + sj)*ldW;
    const float* Xp = X + (size_t)stoks[sj]*ldX;

    for (int k0 = kbeg; k0 < kend; k0 += 8) {
        float4 wv = *(const float4*)&Wp[k0 + shalf*4];
        float4 xv = *(const float4*)&Xp[k0 + shalf*4];
        __syncthreads();
        int kk = shalf*4;
        Ws[kk+0][sj] = wv.x; Ws[kk+1][sj] = wv.y;
        Ws[kk+2][sj] = wv.z; Ws[kk+3][sj] = wv.w;
        Xs[kk+0][sj] = xv.x; Xs[kk+1][sj] = xv.y;
        Xs[kk+2][sj] = xv.z; Xs[kk+3][sj] = xv.w;
        __syncthreads();
        #pragma unroll
        for (int q = 0; q < 8; ++q) {
            float4 x4 = *(const float4*)&Xs[q][rg*4];
            ull w0 = *(const ull*)&Ws[q][cg*8];
            ull w1 = *(const ull*)&Ws[q][cg*8+2];
            ull w2 = *(const ull*)&Ws[q][cg*8+4];
            ull w3 = *(const ull*)&Ws[q][cg*8+6];
            ull xr;
            xr = pack2(x4.x, x4.x);
            acc[0][0]=ffma2(xr,w0,acc[0][0]); acc[0][1]=ffma2(xr,w1,acc[0][1]);
            acc[0][2]=ffma2(xr,w2,acc[0][2]); acc[0][3]=ffma2(xr,w3,acc[0][3]);
            xr = pack2(x4.y, x4.y);
            acc[1][0]=ffma2(xr,w0,acc[1][0]); acc[1][1]=ffma2(xr,w1,acc[1][1]);
            acc[1][2]=ffma2(xr,w2,acc[1][2]); acc[1][3]=ffma2(xr,w3,acc[1][3]);
            xr = pack2(x4.z, x4.z);
            acc[2][0]=ffma2(xr,w0,acc[2][0]); acc[2][1]=ffma2(xr,w1,acc[2][1]);
            acc[2][2]=ffma2(xr,w2,acc[2][2]); acc[2][3]=ffma2(xr,w3,acc[2][3]);
            xr = pack2(x4.w, x4.w);
            acc[3][0]=ffma2(xr,w0,acc[3][0]); acc[3][1]=ffma2(xr,w1,acc[3][1]);
            acc[3][2]=ffma2(xr,w2,acc[3][2]); acc[3][3]=ffma2(xr,w3,acc[3][3]);
        }
    }

    #pragma unroll
    for (int r = 0; r < 4; ++r) {
        int b = rg*4 + r;
        float2 p0 = unpk(acc[r][0]), p1 = unpk(acc[r][1]);
        float2 p2 = unpk(acc[r][2]), p3 = unpk(acc[r][3]);
        float* dst = &g_gpart[y][b][j0 + cg*8];
        *(float4*)dst       = make_float4(p0.x, p0.y, p1.x, p1.y);
        *(float4*)(dst + 4) = make_float4(p2.x, p2.y, p3.x, p3.y);
    }
}

// fixed-order partial sum + biases + activations + state update
__global__ void lstm_epilogue2(const float* __restrict__ bih,
                               const float* __restrict__ bhh,
                               int layer, int nsplit)
{
    int idx = blockIdx.x*blockDim.x + threadIdx.x;
    int b = idx >> 9, jj = idx & 511;
    float* h = layer ? g_h1 : g_h0;
    float* c = layer ? g_c1 : g_c0;
    float s[4];
    #pragma unroll
    for (int g = 0; g < 4; ++g) {
        int col = g*512 + jj;
        float v = bih[col] + bhh[col];
        for (int y = 0; y < nsplit; ++y) v += g_gpart[y][b][col];
        s[g] = v;
    }
    float iv = 1.f/(1.f+expf(-s[0]));
    float fv = 1.f/(1.f+expf(-s[1]));
    float gv = tanhf(s[2]);
    float ov = 1.f/(1.f+expf(-s[3]));
    float cn = fv*c[idx] + iv*gv;
    c[idx] = cn;
    h[idx] = ov*tanhf(cn);
}

// ============================================================================
// FC + partial argmax: tile 128 vocab x 64 batch, 256 threads, 64 out/thread.
// ============================================================================
__global__ void __launch_bounds__(256) fc_argmax2(
    const float* __restrict__ fcW, const float* __restrict__ fcb,
    float* __restrict__ out)
{
    __shared__ __align__(16) float Ws[16][128];
    __shared__ __align__(16) float Hs[16][64];
    __shared__ float rval[BATCH*16];
    __shared__ int   ridx[BATCH*16];

    int tid = threadIdx.x, v0 = blockIdx.x*FC_TILE;
    int l = tid & 31, w = tid >> 5;
    int rg = (w & 1)*8 + (l & 7);     // 0..15 -> batch rows rg*4..+3
    int cg = (w >> 1)*4 + (l >> 3);   // 0..15 -> cols cg*8..+7

    int wj = tid & 127, whalf = tid >> 7;   // W staging
    int hb = tid & 63,  hq = tid >> 6;      // H staging

    ull acc[4][4];
    #pragma unroll
    for (int r = 0; r < 4; ++r)
        #pragma unroll
        for (int u = 0; u < 4; ++u) acc[r][u] = 0ULL;

    const float* Wp = fcW + (size_t)(v0 + wj)*HID;
    const float* Hp = g_h1 + (size_t)hb*HID;

    for (int k0 = 0; k0 < HID; k0 += 16) {
        float4 wa = *(const float4*)&Wp[k0 + whalf*8];
        float4 wb = *(const float4*)&Wp[k0 + whalf*8 + 4];
        float4 hv = *(const float4*)&Hp[k0 + hq*4];
        __syncthreads();
        int kk = whalf*8;
        Ws[kk+0][wj]=wa.x; Ws[kk+1][wj]=wa.y; Ws[kk+2][wj]=wa.z; Ws[kk+3][wj]=wa.w;
        Ws[kk+4][wj]=wb.x; Ws[kk+5][wj]=wb.y; Ws[kk+6][wj]=wb.z; Ws[kk+7][wj]=wb.w;
        int hk = hq*4;
        Hs[hk+0][hb]=hv.x; Hs[hk+1][hb]=hv.y; Hs[hk+2][hb]=hv.z; Hs[hk+3][hb]=hv.w;
        __syncthreads();
        #pragma unroll
        for (int q = 0; q < 16; ++q) {
            float4 x4 = *(const float4*)&Hs[q][rg*4];
            ull w0 = *(const ull*)&Ws[q][cg*8];
            ull w1 = *(const ull*)&Ws[q][cg*8+2];
            ull w2 = *(const ull*)&Ws[q][cg*8+4];
            ull w3 = *(const ull*)&Ws[q][cg*8+6];
            ull xr;
            xr = pack2(x4.x, x4.x);
            acc[0][0]=ffma2(xr,w0,acc[0][0]); acc[0][1]=ffma2(xr,w1,acc[0][1]);
            acc[0][2]=ffma2(xr,w2,acc[0][2]); acc[0][3]=ffma2(xr,w3,acc[0][3]);
            xr = pack2(x4.y, x4.y);
            acc[1][0]=ffma2(xr,w0,acc[1][0]); acc[1][1]=ffma2(xr,w1,acc[1][1]);
            acc[1][2]=ffma2(xr,w2,acc[1][2]); acc[1][3]=ffma2(xr,w3,acc[1][3]);
            xr = pack2(x4.z, x4.z);
            acc[2][0]=ffma2(xr,w0,acc[2][0]); acc[2][1]=ffma2(xr,w1,acc[2][1]);
            acc[2][2]=ffma2(xr,w2,acc[2][2]); acc[2][3]=ffma2(xr,w3,acc[2][3]);
            xr = pack2(x4.w, x4.w);
            acc[3][0]=ffma2(xr,w0,acc[3][0]); acc[3][1]=ffma2(xr,w1,acc[3][1]);
            acc[3][2]=ffma2(xr,w2,acc[3][2]); acc[3][3]=ffma2(xr,w3,acc[3][3]);
        }
    }

    float bv[8];
    #pragma unroll
    for (int u = 0; u < 8; ++u) bv[u] = fcb[v0 + cg*8 + u];

    #pragma unroll
    for (int r = 0; r < 4; ++r) {
        int b = rg*4 + r;
        float vals[8];
        #pragma unroll
        for (int u = 0; u < 4; ++u) {
            float2 t = unpk(acc[r][u]);
            vals[2*u]   = t.x + bv[2*u];
            vals[2*u+1] = t.y + bv[2*u+1];
        }
        float* p = out + (size_t)b*VOCAB + v0 + cg*8;
        *(float4*)p       = make_float4(vals[0],vals[1],vals[2],vals[3]);
        *(float4*)(p + 4) = make_float4(vals[4],vals[5],vals[6],vals[7]);
        float best = vals[0]; int bi = 0;
        #pragma unroll
        for (int u = 1; u < 8; ++u)
            if (vals[u] > best) { best = vals[u]; bi = u; }
        rval[b*16 + cg] = best; ridx[b*16 + cg] = v0 + cg*8 + bi;
    }
    __syncthreads();
    if (tid < BATCH) {
        float best = rval[tid*16]; int bi = ridx[tid*16];
        #pragma unroll
        for (int u = 1; u < 16; ++u) {
            float v = rval[tid*16 + u];
            if (v > best) { best = v; bi = ridx[tid*16 + u]; }
        }
        g_pval[blockIdx.x*BATCH + tid] = best;
        g_pidx[blockIdx.x*BATCH + tid] = bi;
    }
}

// final argmax (ascending scan, lowest-index ties) + token select
__global__ void argmax_token_kernel(const int* __restrict__ target,
                                    const int* __restrict__ tfmask, int t)
{
    __shared__ float sv[256];
    __shared__ int   si[256];
    int tid = threadIdx.x, b = tid>>2, seg = tid&3;
    const int per = (FC_BLOCKS + 3) / 4;
    int s0 = seg*per, s1 = s0 + per; if (s1 > FC_BLOCKS) s1 = FC_BLOCKS;
    float best = -3.4e38f; int bi = 0;
    for (int q = s0; q < s1; ++q) {
        float v = g_pval[q*BATCH + b];
        if (v > best) { best = v; bi = g_pidx[q*BATCH + b]; }
    }
    sv[tid] = best; si[tid] = bi;
    __syncthreads();
    if (seg == 0) {
        #pragma unroll
        for (int u = 1; u < 4; ++u) {
            float v = sv[tid + u];
            if (v > best) { best = v; bi = si[tid + u]; }
        }
        g_xtok[b] = (tfmask[t] > 0) ? target[t*BATCH + b] : bi;
    }
}

extern "C" void kernel_launch(void* const* d_in, const int* in_sizes, int n_in,
                              void* d_out, int out_size)
{
    const float *enc_embed,*dec_embed,*fcW,*fcb;
    const float *eWih0,*eWhh0,*ebih0,*ebhh0,*eWih1,*eWhh1,*ebih1,*ebhh1;
    const float *dWih0,*dWhh0,*dbih0,*dbhh0,*dWih1,*dWhh1,*dbih1,*dbhh1;
    const int *src,*target,*tfmask;

    if (in_sizes[0] == SRCLEN*BATCH) {
        src=(const int*)d_in[0]; target=(const int*)d_in[1]; tfmask=(const int*)d_in[2];
        enc_embed=(const float*)d_in[3]; dec_embed=(const float*)d_in[4];
        eWih0=(const float*)d_in[5];  eWhh0=(const float*)d_in[6];
        ebih0=(const float*)d_in[7];  ebhh0=(const float*)d_in[8];
        eWih1=(const float*)d_in[9];  eWhh1=(const float*)d_in[10];
        ebih1=(const float*)d_in[11]; ebhh1=(const float*)d_in[12];
        dWih0=(const float*)d_in[13]; dWhh0=(const float*)d_in[14];
        dbih0=(const float*)d_in[15]; dbhh0=(const float*)d_in[16];
        dWih1=(const float*)d_in[17]; dWhh1=(const float*)d_in[18];
        dbih1=(const float*)d_in[19]; dbhh1=(const float*)d_in[20];
        fcW=(const float*)d_in[21];   fcb=(const float*)d_in[22];
    } else {
        enc_embed=(const float*)d_in[0];
        eWih0=(const float*)d_in[1];  eWhh0=(const float*)d_in[2];
        ebih0=(const float*)d_in[3];  ebhh0=(const float*)d_in[4];
        eWih1=(const float*)d_in[5];  eWhh1=(const float*)d_in[6];
        ebih1=(const float*)d_in[7];  ebhh1=(const float*)d_in[8];
        dec_embed=(const float*)d_in[9];
        dWih0=(const float*)d_in[10]; dWhh0=(const float*)d_in[11];
        dbih0=(const float*)d_in[12]; dbhh0=(const float*)d_in[13];
        dWih1=(const float*)d_in[14]; dWhh1=(const float*)d_in[15];
        dbih1=(const float*)d_in[16]; dbhh1=(const float*)d_in[17];
        fcW=(const float*)d_in[18];   fcb=(const float*)d_in[19];
        src=(const int*)d_in[20]; target=(const int*)d_in[21]; tfmask=(const int*)d_in[22];
    }

    float* out = (float*)d_out;
    cudaMemsetAsync(out, 0, (size_t)BATCH * VOCAB * sizeof(float));
    init_kernel<<<128, 256>>>(target);

    dim3 g0(32, 12);   // layer0: 4 ih splits (56 each, last 32) + 8 hh splits
    dim3 g1(32, 16);   // layer1: 8 ih + 8 hh splits of 64

    for (int s = 0; s < SRCLEN; ++s) {
        lstm_gates2<<<g0,128>>>(eWih0, EMBD, 4, 56, eWhh0, enc_embed, src + s*BATCH, 0, 0);
        lstm_epilogue2<<<128,256>>>(ebih0, ebhh0, 0, 12);
        lstm_gates2<<<g1,128>>>(eWih1, HID, 8, 64, eWhh1, (const float*)0, (const int*)0, 0, 1);
        lstm_epilogue2<<<128,256>>>(ebih1, ebhh1, 1, 16);
    }
    for (int t = 1; t < TGTLEN; ++t) {
        lstm_gates2<<<g0,128>>>(dWih0, EMBD, 4, 56, dWhh0, dec_embed, (const int*)0, 1, 0);
        lstm_epilogue2<<<128,256>>>(dbih0, dbhh0, 0, 12);
        lstm_gates2<<<g1,128>>>(dWih1, HID, 8, 64, dWhh1, (const float*)0, (const int*)0, 0, 1);
        lstm_epilogue2<<<128,256>>>(dbih1, dbhh1, 1, 16);
        fc_argmax2<<<FC_BLOCKS,256>>>(fcW, fcb, out + (size_t)t*BATCH*VOCAB);
        argmax_token_kernel<<<1,256>>>(target, tfmask, t);
    }
}